// round 17
// baseline (speedup 1.0000x reference)
#include <cuda_runtime.h>
#include <cstddef>

// ---------------------------------------------------------------------------
// Shapes (fixed): B=4, SQ=2048, SK=1024, D=1024
// R16 kernel (best: 1666us) + ONE change: per-thread tile 8x8 -> 8x4 with
// 512-thread CTAs (same 128x128 tile). acc 64->32 regs, target <=64 regs
// => 2 CTAs/SM = 32 warps/SM (8/SMSP), doubling latency-hiding occupancy.
// Layouts, swizzle, pipeline, grids, numerics all unchanged.
// ---------------------------------------------------------------------------
#define BB   4
#define SQ   2048
#define SK   1024
#define DD   1024

__device__ float g_k  [BB * SK * DD];
__device__ float g_v  [BB * SK * DD];
__device__ float g_qy [BB * SQ * DD];
__device__ float g_inv[BB * SQ * DD];
__device__ float g_qk [BB * SQ * SK];

typedef unsigned long long u64;

__device__ __forceinline__ u64 pack_dup(float a) {
    u64 r;
    asm("mov.b64 %0, {%1, %1};" : "=l"(r) : "f"(a));
    return r;
}
__device__ __forceinline__ void fma2(u64 &d, u64 a, u64 b) {
    asm("fma.rn.f32x2 %0, %1, %2, %0;" : "+l"(d) : "l"(a), "l"(b));
}

// B-row swizzle: insert a 4-float gap after every 32 floats (validated R11).
__device__ __forceinline__ int bswz(int f) { return f + 4 * (f >> 5); }
#define RSB 140

// ---------------------------------------------------------------------------
// GEMM tile body: C[m0+128, n0+128] = A * op(B) (+ epilogue)
//   MODEB = 0 : B is [N,K] row-major (NT) — linears, qk
//   MODEB = 1 : B is [K,N] row-major (NN) — attn @ v
//   EPI: 0 = +bias[n] | 1 = /= aux | 2 = none
// 128x128 tile, 512 threads (8 rows x 4 cols per thread), k-slab 16,
// double-buffered smem, reg prefetch, 1 barrier per slab.
// ---------------------------------------------------------------------------
template <int MODEB, int EPI>
__device__ __forceinline__ void run_gemm(
    const float* __restrict__ A, const float* __restrict__ B,
    const float* __restrict__ aux, float* __restrict__ C,
    int N, int K, int m0, int n0)
{
    __shared__ float As[2][16][132];
    __shared__ float Bs[2][16][RSB];

    const int tid = threadIdx.x;
    const int tx = tid & 31;              // 32 col groups x 4 cols
    const int ty = tid >> 5;              // 16 row groups x 8 rows (= warp id)

    // per-thread load coordinates (ONE float4 each for A and B per slab)
    const int lrow = tid >> 2;            // 0..127
    const int lks  = (tid & 3) * 4;       // 0,4,8,12
    const int brow = bswz(lrow);          // swizzled B column (MODEB==0)
    const int bkr  = tid >> 5;            // 0..15   (MODEB==1)
    const int bns  = (tid & 31) * 4;      // 0..124  (MODEB==1)
    const int bnsw = bswz(bns);

    const float* Ag = A + (size_t)(m0 + lrow) * K + lks;
    const float* Bg = (MODEB == 0)
        ? B + (size_t)(n0 + lrow) * K + lks
        : B + (size_t)bkr * N + n0 + bns;

    u64 acc[8][2];
    #pragma unroll
    for (int i = 0; i < 8; i++) {
        acc[i][0] = 0ull;
        acc[i][1] = 0ull;
    }

    const int boff = tx * 4 + 4 * (tx >> 3);   // swizzled B fragment offset
    const int nsl = K >> 4;                    // 16-k slabs

    float4 ra = *(const float4*)Ag;
    float4 rb = *(const float4*)Bg;
    Ag += 16;
    Bg += (MODEB == 0) ? 16 : (size_t)16 * N;

    for (int s = 0; s < nsl; s++) {
        const int buf = s & 1;

        // ---- store staged slab ----
        {
            float* ap = &As[buf][lks][lrow];
            ap[0 * 132] = ra.x;
            ap[1 * 132] = ra.y;
            ap[2 * 132] = ra.z;
            ap[3 * 132] = ra.w;
            if (MODEB == 0) {
                float* bp = &Bs[buf][lks][brow];
                bp[0 * RSB] = rb.x;
                bp[1 * RSB] = rb.y;
                bp[2 * RSB] = rb.z;
                bp[3 * RSB] = rb.w;
            } else {
                *(float4*)&Bs[buf][bkr][bnsw] = rb;
            }
        }
        __syncthreads();

        // ---- prefetch next slab (drains under compute) ----
        if (s + 1 < nsl) {
            ra = *(const float4*)(Ag);
            rb = *(const float4*)(Bg);
            Ag += 16;
            Bg += (MODEB == 0) ? 16 : (size_t)16 * N;
        }

        // ---- compute 16 kk ----
        #pragma unroll
        for (int kk = 0; kk < 16; kk++) {
            float a[8];
            *(float4*)&a[0] = *(const float4*)&As[buf][kk][ty * 8];
            *(float4*)&a[4] = *(const float4*)&As[buf][kk][ty * 8 + 4];
            u64 bv[2];
            const u64* b64 = (const u64*)&Bs[buf][kk][boff];
            bv[0] = b64[0];
            bv[1] = b64[1];
            #pragma unroll
            for (int i = 0; i < 8; i++) {
                u64 ad = pack_dup(a[i]);
                fma2(acc[i][0], ad, bv[0]);
                fma2(acc[i][1], ad, bv[1]);
            }
        }
    }

    // ---- epilogue + store ----
    const int cb = n0 + tx * 4;
    float4 bn;
    if (EPI == 0) bn = *(const float4*)(aux + cb);
    #pragma unroll
    for (int i = 0; i < 8; i++) {
        int r = m0 + ty * 8 + i;
        size_t base = (size_t)r * N + cb;
        float c[4];
        float2 f0 = *(float2*)&acc[i][0];
        float2 f1 = *(float2*)&acc[i][1];
        c[0] = f0.x; c[1] = f0.y; c[2] = f1.x; c[3] = f1.y;
        if (EPI == 0) {
            c[0] += bn.x; c[1] += bn.y; c[2] += bn.z; c[3] += bn.w;
        } else if (EPI == 1) {
            const float4 d = *(const float4*)(aux + base);
            c[0] /= d.x; c[1] /= d.y; c[2] /= d.z; c[3] /= d.w;
        }
        *(float4*)(C + base) = *(float4*)&c[0];
    }
}

// ---------------------------------------------------------------------------
// Fused linears: 1536 CTAs, pointer dispatch only (identical geometry).
// ---------------------------------------------------------------------------
__global__ __launch_bounds__(512, 2) void k_lin4(
    const float* __restrict__ x, const float* __restrict__ y,
    const float* __restrict__ W2, const float* __restrict__ b2,
    const float* __restrict__ W3, const float* __restrict__ b3,
    const float* __restrict__ W4, const float* __restrict__ b4,
    const float* __restrict__ W5, const float* __restrict__ b5,
    float* __restrict__ gk, float* __restrict__ gv,
    float* __restrict__ gqy, float* __restrict__ ginv)
{
    const int t = blockIdx.x;
    const float *A, *B, *bias;
    float* C;
    int u, m0, n0;

    if (t < 256) {
        A = y; B = W2; bias = b2; C = gk;
        u = t;          m0 = (u >> 3) << 7; n0 = (u & 7) << 7;
    } else if (t < 512) {
        A = y; B = W3; bias = b3; C = gv;
        u = t - 256;    m0 = (u >> 3) << 7; n0 = (u & 7) << 7;
    } else if (t < 1024) {
        A = x; B = W4; bias = b4; C = gqy;
        u = t - 512;    m0 = (u >> 3) << 7; n0 = (u & 7) << 7;
    } else {
        A = x; B = W5; bias = b5; C = ginv;
        u = t - 1024;   m0 = (u >> 3) << 7; n0 = (u & 7) << 7;
    }
    run_gemm<0, 0>(A, B, bias, C, DD, DD, m0, n0);
}

// qk = (qy @ k^T) / inv, per batch z
__global__ __launch_bounds__(512, 2) void k_qk(
    const float* __restrict__ gqy, const float* __restrict__ gk,
    const float* __restrict__ ginv, float* __restrict__ gqk)
{
    const size_t z = blockIdx.z;
    run_gemm<0, 1>(gqy + z * ((size_t)SQ * DD),
                   gk  + z * ((size_t)SK * DD),
                   ginv + z * ((size_t)SQ * DD),
                   gqk + z * ((size_t)SQ * SK),
                   SK, DD, blockIdx.y * 128, blockIdx.x * 128);
}

// out = attn @ v, per batch z (v natural [s][d], MODEB=1)
__global__ __launch_bounds__(512, 2) void k_av(
    const float* __restrict__ gqk, const float* __restrict__ gv,
    float* __restrict__ out)
{
    const size_t z = blockIdx.z;
    run_gemm<1, 2>(gqk + z * ((size_t)SQ * SK),
                   gv  + z * ((size_t)SK * DD),
                   nullptr,
                   out + z * ((size_t)SQ * DD),
                   DD, SK, blockIdx.y * 128, blockIdx.x * 128);
}

// ---------------------------------------------------------------------------
// Row softmax over N=1024, one 256-thread block per row, in place.
// ---------------------------------------------------------------------------
__global__ __launch_bounds__(256) void softmax1024(float* __restrict__ data)
{
    float* p = data + (size_t)blockIdx.x * 1024;
    const int t    = threadIdx.x;
    const int lane = t & 31;
    const int warp = t >> 5;

    __shared__ float redbuf[8];
    __shared__ float stat[2];

    float4 x = *((const float4*)p + t);

    float m = fmaxf(fmaxf(x.x, x.y), fmaxf(x.z, x.w));
    #pragma unroll
    for (int o = 16; o > 0; o >>= 1)
        m = fmaxf(m, __shfl_xor_sync(0xffffffffu, m, o));
    if (lane == 0) redbuf[warp] = m;
    __syncthreads();
    if (t == 0) {
        float mm = redbuf[0];
        #pragma unroll
        for (int i = 1; i < 8; i++) mm = fmaxf(mm, redbuf[i]);
        stat[0] = mm;
    }
    __syncthreads();
    const float bm = stat[0];

    x.x = __expf(x.x - bm);
    x.y = __expf(x.y - bm);
    x.z = __expf(x.z - bm);
    x.w = __expf(x.w - bm);

    float s = (x.x + x.y) + (x.z + x.w);
    #pragma unroll
    for (int o = 16; o > 0; o >>= 1)
        s += __shfl_xor_sync(0xffffffffu, s, o);
    __syncthreads();
    if (lane == 0) redbuf[warp] = s;
    __syncthreads();
    if (t == 0) {
        float ss = redbuf[0];
        #pragma unroll
        for (int i = 1; i < 8; i++) ss += redbuf[i];
        stat[1] = 1.0f / ss;
    }
    __syncthreads();
    const float r = stat[1];

    x.x *= r; x.y *= r; x.z *= r; x.w *= r;
    *((float4*)p + t) = x;
}

// ---------------------------------------------------------------------------
// kernel_launch
// inputs: 0:x 1:y 2:W1 3:b1 4:W2 5:b2 6:W3 7:b3 8:W4 9:b4 10:W5 11:b5
// ---------------------------------------------------------------------------
extern "C" void kernel_launch(void* const* d_in, const int* in_sizes, int n_in,
                              void* d_out, int out_size)
{
    (void)in_sizes; (void)n_in; (void)out_size;

    const float* x  = (const float*)d_in[0];
    const float* y  = (const float*)d_in[1];
    const float* W2 = (const float*)d_in[4];
    const float* b2 = (const float*)d_in[5];
    const float* W3 = (const float*)d_in[6];
    const float* b3 = (const float*)d_in[7];
    const float* W4 = (const float*)d_in[8];
    const float* b4 = (const float*)d_in[9];
    const float* W5 = (const float*)d_in[10];
    const float* b5 = (const float*)d_in[11];
    float* out = (float*)d_out;

    void *pk, *pv, *pqy, *pinv, *pqk;
    cudaGetSymbolAddress(&pk,   g_k);
    cudaGetSymbolAddress(&pv,   g_v);
    cudaGetSymbolAddress(&pqy,  g_qy);
    cudaGetSymbolAddress(&pinv, g_inv);
    cudaGetSymbolAddress(&pqk,  g_qk);
    float* gk   = (float*)pk;
    float* gv   = (float*)pv;
    float* gqy  = (float*)pqy;
    float* ginv = (float*)pinv;
    float* gqk  = (float*)pqk;

    const dim3 blk(512);

    // 1) four independent linears, one 1536-CTA launch
    k_lin4<<<1536, blk>>>(x, y, W2, b2, W3, b3, W4, b4, W5, b5,
                          gk, gv, gqy, ginv);

    // 2) qk = (qy @ k^T) / inv, per batch
    k_qk<<<dim3(SK / 128, SQ / 128, BB), blk>>>(gqy, gk, ginv, gqk);

    // 3) softmax rows (B*SQ rows of SK=1024)
    softmax1024<<<BB * SQ, 256>>>(gqk);

    // 4) out = attn @ v, per batch
    k_av<<<dim3(DD / 128, SQ / 128, BB), blk>>>(gqk, gv, out);
}